// round 16
// baseline (speedup 1.0000x reference)
#include <cuda_runtime.h>
#include <cstdint>

#define NC 1024
#define G  256
#define M  2
#define NTI 16                   // i-tiles (16 rows)
#define NTJ 32                   // j-tiles (8 cols)
#define XTOT (M * G * G * 2)

typedef unsigned long long u64;

// TRANSPOSED axis weights: g_W[axis][m][c][i]  (i contiguous)
__device__ float g_W[2][M][NC][G];             // 4 MB
__device__ int   g_len[M][NTI][NTJ];
__device__ int   g_list[M][NTI][NTJ][NC];      // 4 MB
__device__ float g_rl[2];                      // reciprocal lengthscales

// ---- packed f32x2 helpers ----
__device__ __forceinline__ u64 pack2(float lo, float hi) {
    u64 r; asm("mov.b64 %0, {%1, %2};" : "=l"(r) : "f"(lo), "f"(hi)); return r;
}
__device__ __forceinline__ void unpack2(float& lo, float& hi, u64 v) {
    asm("mov.b64 {%0, %1}, %2;" : "=f"(lo), "=f"(hi) : "l"(v));
}
__device__ __forceinline__ void ffma2(u64& d, u64 a, u64 b) {
    asm("fma.rn.f32x2 %0, %1, %2, %0;" : "+l"(d) : "l"(a), "l"(b));
}

// ---------------------------------------------------------------------------
// Kernel 0: compute reciprocal lengthscales once (softplus is expensive)
// ---------------------------------------------------------------------------
__global__ void setup_kernel(const float* __restrict__ lsp) {
    int t = threadIdx.x;
    if (t < 2) g_rl[t] = 1.0f / (1e-5f + log1pf(expf(lsp[t])));
}

// ---------------------------------------------------------------------------
// Kernel 1: build Wx/Wy transposed (reads precomputed g_rl)
// ---------------------------------------------------------------------------
__global__ void weights_kernel(const float* __restrict__ xc) {
    int idx = blockIdx.x * blockDim.x + threadIdx.x;   // 1,048,576
    int i = idx & (G - 1);
    int c = (idx >> 8) & (NC - 1);
    int d = (idx >> 18) & 1;
    int m = idx >> 19;
    float rl = g_rl[d];
    float g = 1.0f + (float)(i - 128) * (1.0f / 64.0f);
    float x = xc[(m * NC + c) * 2 + d];
    float t = (g - x) * rl;
    g_W[d][m][c][i] = __expf(-0.5f * t * t);
}

// ---------------------------------------------------------------------------
// Kernel 2: per-halftile c-list compaction (one warp per 16x8 tile)
// ---------------------------------------------------------------------------
__global__ void compact_kernel(const float* __restrict__ xc) {
    int warp = (blockIdx.x * blockDim.x + threadIdx.x) >> 5;
    int lane = threadIdx.x & 31;
    if (warp >= M * NTI * NTJ) return;
    int jT = warp & (NTJ - 1);
    int iT = (warp >> 5) & (NTI - 1);
    int m  = warp >> 9;

    float rlx = g_rl[0], rly = g_rl[1];
    float x0 = 1.0f + (float)(iT * 16 - 128) * (1.0f / 64.0f);
    float x1 = x0 + 15.0f / 64.0f;
    float y0 = 1.0f + (float)(jT * 8 - 128) * (1.0f / 64.0f);
    float y1 = y0 + 7.0f / 64.0f;
    const float thr = 27.63f;   // weight cutoff ~1e-6

    int count = 0;
    int* lst = g_list[m][iT][jT];
    for (int c0 = 0; c0 < NC; c0 += 32) {
        int c = c0 + lane;
        float cx = xc[(m * NC + c) * 2 + 0];
        float cy = xc[(m * NC + c) * 2 + 1];
        float dx = fmaxf(fmaxf(x0 - cx, cx - x1), 0.0f) * rlx;
        float dy = fmaxf(fmaxf(y0 - cy, cy - y1), 0.0f) * rly;
        bool keep = (dx * dx + dy * dy) <= thr;
        unsigned mask = __ballot_sync(0xffffffffu, keep);
        int off = __popc(mask & ((1u << lane) - 1u));
        if (keep) lst[count + off] = c;
        count += __popc(mask);
    }
    if (lane == 0) g_len[m][iT][jT] = count;
}

// ---------------------------------------------------------------------------
// Kernel 3: warp-autonomous contraction. CTA = 16x8 half-tile, 256 threads.
// 8 warps = 2 patches (4 j-cols) x 4 c-segments. NO barrier/smem in mainloop.
// Lane = (i = lane&15) x (j-pair via jo = lane>>4). 2 positions x 17 ch.
// One __syncthreads at the end: segs 1-3 -> smem, seg 0 reduces + stores.
// ---------------------------------------------------------------------------
__global__ __launch_bounds__(256)
void setconv_kernel(const float* __restrict__ yc, float* __restrict__ out) {
    __shared__ float red[3][2][64][18];   // [seg-1][patch][pos][ch] 27.6 KB

    const int jT = blockIdx.x;
    const int iT = blockIdx.y;
    const int m  = blockIdx.z;
    const int tid = threadIdx.x;
    const int lane = tid & 31;
    const int wid  = tid >> 5;
    const int patch = wid & 1;     // 2 patches of 4 j-cols
    const int seg   = wid >> 1;    // 4 c-segments
    const int li = lane & 15;
    const int jo = lane >> 4;      // 0/1 -> j-pair within patch
    const int iBase = iT * 16;
    const int jBase = jT * 8;
    const int i  = iBase + li;
    const int jP = jBase + patch * 4 + jo * 2;   // lane's j-pair base

    const int len = g_len[m][iT][jT];
    float* outZ = out + (size_t)XTOT;

    if (len == 0) {                 // uniform per CTA: no barrier below runs
        if (seg == 0) {
#pragma unroll
            for (int dj = 0; dj < 2; dj++) {
                int j = jP + dj;
                float2 g2;
                g2.x = 1.0f + (float)(i - 128) * (1.0f / 64.0f);
                g2.y = 1.0f + (float)(j - 128) * (1.0f / 64.0f);
                ((float2*)out)[(size_t)(m * G + i) * G + j] = g2;
                float* zo = outZ + ((size_t)((m * G + i) * G + j)) * 17;
#pragma unroll
                for (int k = 0; k < 17; k++) zo[k] = 0.0f;
            }
        }
        return;
    }

    const int* __restrict__ lst = g_list[m][iT][jT];
    const ulonglong2* __restrict__ ycv = (const ulonglong2*)yc;

    const int qseg = (len + 3) >> 2;
    const int lo = seg * qseg;
    const int hi = min(lo + qseg, len);

    u64 aA[8], aB[8];
#pragma unroll
    for (int k = 0; k < 8; k++) { aA[k] = 0ull; aB[k] = 0ull; }
    float dA = 0.0f, dB = 0.0f;

    const float* __restrict__ Wx = &g_W[0][m][0][iBase + li];
    const float* __restrict__ Wy = &g_W[1][m][0][jP];

#pragma unroll 2
    for (int cp = lo; cp < hi; ++cp) {
        int cidx = lst[cp];
        float wx = Wx[cidx << 8];                                  // g_W[0][m][cidx][iBase+li]
        float2 wy = *(const float2*)(Wy + (cidx << 8));            // g_W[1][m][cidx][jP..+1]
        const ulonglong2* yr = ycv + (size_t)((m * NC + cidx) << 2);
        ulonglong2 y0 = yr[0], y1 = yr[1], y2 = yr[2], y3 = yr[3];
        float w0 = wx * wy.x, w1 = wx * wy.y;
        dA += w0; dB += w1;
        u64 p0 = pack2(w0, w0), p1 = pack2(w1, w1);
        ffma2(aA[0], p0, y0.x); ffma2(aA[1], p0, y0.y);
        ffma2(aA[2], p0, y1.x); ffma2(aA[3], p0, y1.y);
        ffma2(aA[4], p0, y2.x); ffma2(aA[5], p0, y2.y);
        ffma2(aA[6], p0, y3.x); ffma2(aA[7], p0, y3.y);
        ffma2(aB[0], p1, y0.x); ffma2(aB[1], p1, y0.y);
        ffma2(aB[2], p1, y1.x); ffma2(aB[3], p1, y1.y);
        ffma2(aB[4], p1, y2.x); ffma2(aB[5], p1, y2.y);
        ffma2(aB[6], p1, y3.x); ffma2(aB[7], p1, y3.y);
    }

    // patch-local position indices: q0 = jo*32 + li (dj=0), q1 = q0+16 (dj=1)
    const int q0 = jo * 32 + li;

    if (seg > 0) {
        float* r0 = &red[seg - 1][patch][q0][0];
        float* r1 = &red[seg - 1][patch][q0 + 16][0];
#pragma unroll
        for (int k = 0; k < 8; k++) {
            unpack2(r0[2 * k], r0[2 * k + 1], aA[k]);
            unpack2(r1[2 * k], r1[2 * k + 1], aB[k]);
        }
        r0[16] = dA; r1[16] = dB;
    }
    __syncthreads();
    if (seg > 0) return;

    // seg 0 reduces (fixed order: own + seg1 + seg2 + seg3) and stores
#pragma unroll
    for (int dj = 0; dj < 2; dj++) {
        int j = jP + dj;
        int q = q0 + dj * 16;
        float o[17];
        u64* acc = dj ? aB : aA;
#pragma unroll
        for (int k = 0; k < 8; k++) unpack2(o[2 * k], o[2 * k + 1], acc[k]);
        o[16] = dj ? dB : dA;
#pragma unroll
        for (int s = 0; s < 3; s++) {
            const float* r = &red[s][patch][q][0];
#pragma unroll
            for (int k = 0; k < 17; k++) o[k] += r[k];
        }
        float2 g2;
        g2.x = 1.0f + (float)(i - 128) * (1.0f / 64.0f);
        g2.y = 1.0f + (float)(j - 128) * (1.0f / 64.0f);
        ((float2*)out)[(size_t)(m * G + i) * G + j] = g2;
        float* zo = outZ + ((size_t)((m * G + i) * G + j)) * 17;
#pragma unroll
        for (int k = 0; k < 17; k++) zo[k] = o[k];
    }
}

// ---------------------------------------------------------------------------
extern "C" void kernel_launch(void* const* d_in, const int* in_sizes, int n_in,
                              void* d_out, int out_size) {
    const float* xc  = (const float*)d_in[0];  // [2,1024,2]
    const float* yc  = (const float*)d_in[1];  // [2,1024,16]
    const float* lsp = (const float*)d_in[3];  // [2]
    float* out = (float*)d_out;

    setup_kernel<<<1, 32>>>(lsp);
    weights_kernel<<<(M * 2 * G * NC) / 256, 256>>>(xc);
    compact_kernel<<<(M * NTI * NTJ * 32) / 256, 256>>>(xc);
    dim3 g(NTJ, NTI, M);
    setconv_kernel<<<g, 256>>>(yc, out);
}

// round 17
// speedup vs baseline: 1.1934x; 1.1934x over previous
#include <cuda_runtime.h>
#include <cstdint>

#define NC 1024
#define G  256
#define M  2
#define CH 128
#define NT 16                    // tiles per dim
#define NTILES (M * NT * NT)     // 512
#define XTOT (M * G * G * 2)

typedef unsigned long long u64;

// TRANSPOSED axis weights: g_W[axis][m][c][i]  (i contiguous)
__device__ float g_W[2][M][NC][G];            // 4 MB
__device__ int   g_len[M][NT][NT];
__device__ int   g_list[M][NT][NT][NC];       // 2 MB
__device__ float g_rl[2];                     // reciprocal lengthscales

// ---- packed f32x2 helpers ----
__device__ __forceinline__ u64 pack2(float lo, float hi) {
    u64 r; asm("mov.b64 %0, {%1, %2};" : "=l"(r) : "f"(lo), "f"(hi)); return r;
}
__device__ __forceinline__ void unpack2(float& lo, float& hi, u64 v) {
    asm("mov.b64 {%0, %1}, %2;" : "=f"(lo), "=f"(hi) : "l"(v));
}
__device__ __forceinline__ void ffma2(u64& d, u64 a, u64 b) {
    asm("fma.rn.f32x2 %0, %1, %2, %0;" : "+l"(d) : "l"(a), "l"(b));
}
__device__ __forceinline__ void lds_v2_f32(float& a, float& b, uint32_t addr) {
    asm volatile("ld.shared.v2.f32 {%0, %1}, [%2];" : "=f"(a), "=f"(b) : "r"(addr));
}
__device__ __forceinline__ void cpasync16(uint32_t dst, const void* src, int src_bytes) {
    asm volatile("cp.async.cg.shared.global [%0], [%1], 16, %2;"
                 :: "r"(dst), "l"(src), "r"(src_bytes));
}
__device__ __forceinline__ void cpasync_commit() {
    asm volatile("cp.async.commit_group;");
}
template <int N>
__device__ __forceinline__ void cpasync_wait() {
    asm volatile("cp.async.wait_group %0;" :: "n"(N));
}

// ---------------------------------------------------------------------------
// Kernel 0: reciprocal lengthscales (softplus once, not 1M times)
// ---------------------------------------------------------------------------
__global__ void setup_kernel(const float* __restrict__ lsp) {
    int t = threadIdx.x;
    if (t < 2) g_rl[t] = 1.0f / (1e-5f + log1pf(expf(lsp[t])));
}

// ---------------------------------------------------------------------------
// Kernel 1: build Wx/Wy transposed (reads g_rl; no per-thread softplus)
// ---------------------------------------------------------------------------
__global__ void weights_kernel(const float* __restrict__ xc) {
    int idx = blockIdx.x * blockDim.x + threadIdx.x;   // 1,048,576
    int i = idx & (G - 1);
    int c = (idx >> 8) & (NC - 1);
    int d = (idx >> 18) & 1;
    int m = idx >> 19;
    float rl = g_rl[d];
    float g = 1.0f + (float)(i - 128) * (1.0f / 64.0f);
    float x = xc[(m * NC + c) * 2 + d];
    float t = (g - x) * rl;
    g_W[d][m][c][i] = __expf(-0.5f * t * t);
}

// ---------------------------------------------------------------------------
// Kernel 2: per-tile c-list compaction (one warp per 16x16 tile)
// ---------------------------------------------------------------------------
__global__ void compact_kernel(const float* __restrict__ xc) {
    int warp = (blockIdx.x * blockDim.x + threadIdx.x) >> 5;
    int lane = threadIdx.x & 31;
    if (warp >= NTILES) return;
    int jT = warp & (NT - 1);
    int iT = (warp >> 4) & (NT - 1);
    int m  = warp >> 8;

    float rlx = g_rl[0], rly = g_rl[1];
    float x0 = 1.0f + (float)(iT * 16 - 128) * (1.0f / 64.0f);
    float x1 = x0 + 15.0f / 64.0f;
    float y0 = 1.0f + (float)(jT * 16 - 128) * (1.0f / 64.0f);
    float y1 = y0 + 15.0f / 64.0f;
    const float thr = 21.0f;   // weight cutoff ~2.7e-5 (tightened R17)

    int count = 0;
    int* lst = g_list[m][iT][jT];
    for (int c0 = 0; c0 < NC; c0 += 32) {
        int c = c0 + lane;
        float cx = xc[(m * NC + c) * 2 + 0];
        float cy = xc[(m * NC + c) * 2 + 1];
        float dx = fmaxf(fmaxf(x0 - cx, cx - x1), 0.0f) * rlx;
        float dy = fmaxf(fmaxf(y0 - cy, cy - y1), 0.0f) * rly;
        bool keep = (dx * dx + dy * dy) <= thr;
        unsigned mask = __ballot_sync(0xffffffffu, keep);
        int off = __popc(mask & ((1u << lane) - 1u));
        if (keep) lst[count + off] = c;
        count += __popc(mask);
    }
    if (lane == 0) g_len[m][iT][jT] = count;
}

// ---------------------------------------------------------------------------
// Kernel 3: register-blocked contraction (2i x 2j x 4k per thread), CH=128,
// cp.async double-buffered. Grid coords folded into epilogue.
// ---------------------------------------------------------------------------
__global__ __launch_bounds__(256, 4)
void setconv_kernel(const float* __restrict__ yc, float* __restrict__ out) {
    __shared__ float  wxs[2][CH][16];   // 16 KB
    __shared__ float  wys[2][CH][16];   // 16 KB
    __shared__ float4 ycs[2][CH][4];    // 16 KB  (total 48 KB)

    const int tile = blockIdx.x;
    const int jT = tile & (NT - 1);
    const int iT = (tile >> 4) & (NT - 1);
    const int m  = tile >> 8;
    const int tid = threadIdx.x;
    const int tj2 = tid & 7;
    const int ti2 = (tid >> 3) & 7;
    const int tk  = tid >> 6;           // 0..3, uniform per warp-pair
    const int iBase = iT * 16;
    const int jBase = jT * 16;

    // x_grid_b coords (tk==0 threads: 4 positions each -> full tile)
    if (tk == 0) {
#pragma unroll
        for (int di = 0; di < 2; di++) {
#pragma unroll
            for (int dj = 0; dj < 2; dj++) {
                int i = iBase + ti2 * 2 + di;
                int j = jBase + tj2 * 2 + dj;
                float2 g2;
                g2.x = 1.0f + (float)(i - 128) * (1.0f / 64.0f);
                g2.y = 1.0f + (float)(j - 128) * (1.0f / 64.0f);
                ((float2*)out)[(size_t)(m * G + i) * G + j] = g2;
            }
        }
    }

    const int len = g_len[m][iT][jT];
    const int* __restrict__ lst = g_list[m][iT][jT];
    const float4* __restrict__ yc4 = (const float4*)yc;

    const uint32_t wxs_s = (uint32_t)__cvta_generic_to_shared(&wxs[0][0][0]);
    const uint32_t wys_s = (uint32_t)__cvta_generic_to_shared(&wys[0][0][0]);
    const uint32_t ycs_s = (uint32_t)__cvta_generic_to_shared(&ycs[0][0][0]);

    const int nchunk = (len + CH - 1) / CH;

    // staging: 512 quads per array; each thread does 2 per array
    auto stage = [&](int buf, int c0) {
        uint32_t boff = (uint32_t)buf * (CH * 16 * 4);
#pragma unroll
        for (int r = 0; r < 2; r++) {
            int u = tid + r * 256;          // 0..511
            int cc = u >> 2, q = u & 3;
            int cpos = c0 + cc;
            bool v = cpos < len;
            int cidx = v ? lst[cpos] : 0;
            int b16 = v ? 16 : 0;
            uint32_t doff = boff + (uint32_t)(cc * 16 + q * 4) * 4;
            cpasync16(wxs_s + doff, &g_W[0][m][cidx][iBase + q * 4], b16);
            cpasync16(wys_s + doff, &g_W[1][m][cidx][jBase + q * 4], b16);
            cpasync16(ycs_s + doff, &yc4[((m * NC + cidx) << 2) + q], b16);
        }
        cpasync_commit();
    };

    u64 acc2[4][2];
#pragma unroll
    for (int a = 0; a < 4; a++) { acc2[a][0] = 0ull; acc2[a][1] = 0ull; }
    float accD[4] = {0.0f, 0.0f, 0.0f, 0.0f};

    if (nchunk > 0) {
        stage(0, 0);
        for (int t = 0; t < nchunk; t++) {
            int cur = t & 1;
            if (t + 1 < nchunk) {
                stage(cur ^ 1, (t + 1) * CH);
                cpasync_wait<1>();
            } else {
                cpasync_wait<0>();
            }
            __syncthreads();

            const uint32_t bo = (uint32_t)cur * (CH * 16 * 4);
            const uint32_t wx_a = wxs_s + bo + (uint32_t)ti2 * 8;
            const uint32_t wy_a = wys_s + bo + (uint32_t)tj2 * 8;
            const uint32_t yc_a = ycs_s + bo + (uint32_t)tk * 16;

            if (tk == 3) {
#pragma unroll 8
                for (int cc = 0; cc < CH; ++cc) {
                    float wx0, wx1, wy0, wy1;
                    lds_v2_f32(wx0, wx1, wx_a + cc * 64);
                    lds_v2_f32(wy0, wy1, wy_a + cc * 64);
                    u64 y01, y23;
                    asm volatile("ld.shared.v2.b64 {%0, %1}, [%2];"
                                 : "=l"(y01), "=l"(y23) : "r"(yc_a + cc * 64));
                    float w00 = wx0 * wy0, w01 = wx0 * wy1;
                    float w10 = wx1 * wy0, w11 = wx1 * wy1;
                    accD[0] += w00; accD[1] += w01; accD[2] += w10; accD[3] += w11;
                    u64 p00 = pack2(w00, w00), p01 = pack2(w01, w01);
                    u64 p10 = pack2(w10, w10), p11 = pack2(w11, w11);
                    ffma2(acc2[0][0], p00, y01); ffma2(acc2[0][1], p00, y23);
                    ffma2(acc2[1][0], p01, y01); ffma2(acc2[1][1], p01, y23);
                    ffma2(acc2[2][0], p10, y01); ffma2(acc2[2][1], p10, y23);
                    ffma2(acc2[3][0], p11, y01); ffma2(acc2[3][1], p11, y23);
                }
            } else {
#pragma unroll 8
                for (int cc = 0; cc < CH; ++cc) {
                    float wx0, wx1, wy0, wy1;
                    lds_v2_f32(wx0, wx1, wx_a + cc * 64);
                    lds_v2_f32(wy0, wy1, wy_a + cc * 64);
                    u64 y01, y23;
                    asm volatile("ld.shared.v2.b64 {%0, %1}, [%2];"
                                 : "=l"(y01), "=l"(y23) : "r"(yc_a + cc * 64));
                    float w00 = wx0 * wy0, w01 = wx0 * wy1;
                    float w10 = wx1 * wy0, w11 = wx1 * wy1;
                    u64 p00 = pack2(w00, w00), p01 = pack2(w01, w01);
                    u64 p10 = pack2(w10, w10), p11 = pack2(w11, w11);
                    ffma2(acc2[0][0], p00, y01); ffma2(acc2[0][1], p00, y23);
                    ffma2(acc2[1][0], p01, y01); ffma2(acc2[1][1], p01, y23);
                    ffma2(acc2[2][0], p10, y01); ffma2(acc2[2][1], p10, y23);
                    ffma2(acc2[3][0], p11, y01); ffma2(acc2[3][1], p11, y23);
                }
            }
            __syncthreads();
        }
    }

    // --- epilogue: 4 positions x 4 channels (+density for tk==3) ---
    float* outZ = out + (size_t)XTOT;
#pragma unroll
    for (int di = 0; di < 2; di++) {
#pragma unroll
        for (int dj = 0; dj < 2; dj++) {
            int ij = di * 2 + dj;
            int i = iBase + ti2 * 2 + di;
            int j = jBase + tj2 * 2 + dj;
            float* zo = outZ + ((size_t)((m * G + i) * G + j)) * 17 + tk * 4;
            float a0, a1, a2, a3;
            unpack2(a0, a1, acc2[ij][0]);
            unpack2(a2, a3, acc2[ij][1]);
            zo[0] = a0; zo[1] = a1; zo[2] = a2; zo[3] = a3;
            if (tk == 3) zo[4] = accD[ij];
        }
    }
}

// ---------------------------------------------------------------------------
extern "C" void kernel_launch(void* const* d_in, const int* in_sizes, int n_in,
                              void* d_out, int out_size) {
    const float* xc  = (const float*)d_in[0];  // [2,1024,2]
    const float* yc  = (const float*)d_in[1];  // [2,1024,16]
    const float* lsp = (const float*)d_in[3];  // [2]
    float* out = (float*)d_out;

    setup_kernel<<<1, 32>>>(lsp);
    weights_kernel<<<(M * 2 * G * NC) / 256, 256>>>(xc);
    compact_kernel<<<(NTILES * 32) / 256, 256>>>(xc);
    setconv_kernel<<<NTILES, 256>>>(yc, out);
}